// round 12
// baseline (speedup 1.0000x reference)
#include <cuda_runtime.h>
#include <cuda_bf16.h>
#include <mma.h>
#include <math.h>
#include <stdint.h>

using namespace nvcuda;

#define N_   64
#define C_   512
#define P_   1024
#define KA   65
#define KC   64
#define EPSF 1e-12f

// ---------------- scratch (device globals: allocation-free) ----------------
__device__ float         g_inv[N_ * P_];             // per-pixel 1/||x||
__device__ __nv_bfloat16 g_a[N_ * KC * P_];          // a' = softmax * inv, bf16
__device__ __nv_bfloat16 g_xb[N_ * C_ * P_];         // bf16 copy of x (64 MB)
__device__ float         g_agg[N_ * KC * C_];
__device__ float         g_nsq[N_];

#define LDA1 72      // ws leading dim (k-major w tile), elems
#define LDXS 136     // [c][p] tile leading dim (128 px + 8 pad), elems
#define LDO1 84      // f32 out tile leading dim, elems

__device__ __forceinline__ uint32_t bfpack(float a, float b) {
    __nv_bfloat162 h = __floats2bfloat162_rn(a, b);
    return *reinterpret_cast<uint32_t*>(&h);
}

// ============ GEMM1: logits (tensor cores) + fused L2 norm + softmax ============
// Per CTA: sample n, 128-pixel tile.  D[p=128, k=80pad] = A[p,c] * W[k,c]^T,
// K = 512 channels in 8 chunks of 64.  x staged in native [c][p] layout;
// bf16(x) is also streamed to g_xb for gemm2.  Epilogue stores a' = a * inv.
__global__ void __launch_bounds__(128) k_gemm1(const float* __restrict__ x,
                                               const float* __restrict__ w,
                                               const float* __restrict__ b) {
    // union: { ws[80][72]bf16 (11520B) | xa[64][136]bf16 (17408B) } vs outp[128][84]f32
    __shared__ __align__(16) char smbuf[43008];
    __shared__ float bs[KA];
    __shared__ float sq[4][128];                  // per-warp sumsq partials
    __nv_bfloat16* ws = reinterpret_cast<__nv_bfloat16*>(smbuf);
    __nv_bfloat16* xa = reinterpret_cast<__nv_bfloat16*>(smbuf + 11520);
    float* outp = reinterpret_cast<float*>(smbuf);

    int n = blockIdx.x;
    int pblk = blockIdx.y * 128;
    int tid = threadIdx.x;
    int wid = tid >> 5;
    int lane = tid & 31;
    int px4 = 4 * lane;                           // this thread's 4 pixels
    if (tid < KA) bs[tid] = b[tid];

    wmma::fragment<wmma::accumulator, 16, 16, 16, float> acc[2][5];
#pragma unroll
    for (int i = 0; i < 2; i++)
#pragma unroll
        for (int j = 0; j < 5; j++) wmma::fill_fragment(acc[i][j], 0.f);

    float sqa[4] = {0.f, 0.f, 0.f, 0.f};
    const float* xg = x + (size_t)n * C_ * P_ + pblk;
    __nv_bfloat16* xbg = g_xb + (size_t)n * C_ * P_ + pblk;
    uint32_t xr[32];   // packed bf16x2: 16 (row, 4px) pieces
    uint32_t wr[20];   // packed bf16x2: w chunk share

#define G1_LOAD(c0_)                                                           \
    do {                                                                       \
        _Pragma("unroll")                                                      \
        for (int i = 0; i < 16; i++) {                                         \
            int c = (c0_) + wid + 4 * i;                                       \
            float4 v = *reinterpret_cast<const float4*>(xg + (size_t)c * P_ + px4); \
            sqa[0] = fmaf(v.x, v.x, sqa[0]);                                   \
            sqa[1] = fmaf(v.y, v.y, sqa[1]);                                   \
            sqa[2] = fmaf(v.z, v.z, sqa[2]);                                   \
            sqa[3] = fmaf(v.w, v.w, sqa[3]);                                   \
            xr[2 * i]     = bfpack(v.x, v.y);                                  \
            xr[2 * i + 1] = bfpack(v.z, v.w);                                  \
        }                                                                      \
        _Pragma("unroll")                                                      \
        for (int i = 0; i < 20; i++) {                                         \
            int r = wid + 4 * i;                                               \
            float f0 = 0.f, f1 = 0.f;                                          \
            if (r < KA) {                                                      \
                float2 v = *reinterpret_cast<const float2*>(                   \
                    w + r * C_ + (c0_) + 2 * lane);                            \
                f0 = v.x; f1 = v.y;                                            \
            }                                                                  \
            wr[i] = bfpack(f0, f1);                                            \
        }                                                                      \
    } while (0)

    G1_LOAD(0);

    for (int ch = 0; ch < 8; ch++) {
        __syncthreads();   // previous mma done reading smem
#pragma unroll
        for (int i = 0; i < 16; i++) {
            int row = wid + 4 * i;    // local channel row
            uint2 pk = make_uint2(xr[2 * i], xr[2 * i + 1]);
            *reinterpret_cast<uint2*>(&xa[row * LDXS + px4]) = pk;
            // stream bf16(x) to global for gemm2 (coalesced 256B per warp)
            *reinterpret_cast<uint2*>(xbg + (size_t)(ch * 64 + row) * P_ + px4) = pk;
        }
#pragma unroll
        for (int i = 0; i < 20; i++)
            *reinterpret_cast<uint32_t*>(&ws[(wid + 4 * i) * LDA1 + 2 * lane]) = wr[i];
        __syncthreads();

        if (ch < 7) G1_LOAD((ch + 1) * 64);   // LDGs in flight during mma below

#pragma unroll
        for (int ks = 0; ks < 4; ks++) {
            // A[p, c] tile is xa[c][p]: col_major, ldm = LDXS
            wmma::fragment<wmma::matrix_a, 16, 16, 16, __nv_bfloat16, wmma::col_major> af[2];
#pragma unroll
            for (int i = 0; i < 2; i++)
                wmma::load_matrix_sync(af[i], xa + (16 * ks) * LDXS + 32 * wid + 16 * i, LDXS);
#pragma unroll
            for (int j = 0; j < 5; j++) {
                wmma::fragment<wmma::matrix_b, 16, 16, 16, __nv_bfloat16, wmma::col_major> bf;
                wmma::load_matrix_sync(bf, ws + (16 * j) * LDA1 + 16 * ks, LDA1);
#pragma unroll
                for (int i = 0; i < 2; i++) wmma::mma_sync(acc[i][j], af[i], bf, acc[i][j]);
            }
        }
    }
#undef G1_LOAD

    // publish sumsq partials (4 pixels per thread, one slot per warp)
#pragma unroll
    for (int j = 0; j < 4; j++) sq[wid][px4 + j] = sqa[j];

    __syncthreads();   // smem reuse: bf16 tiles -> f32 out tile
#pragma unroll
    for (int i = 0; i < 2; i++)
#pragma unroll
        for (int j = 0; j < 5; j++)
            wmma::store_matrix_sync(outp + (32 * wid + 16 * i) * LDO1 + 16 * j,
                                    acc[i][j], LDO1, wmma::mem_row_major);
    __syncthreads();

    // epilogue: thread = pixel. logits = D*inv + b ; softmax ; store a' = a*inv
    float sumsq = sq[0][tid] + sq[1][tid] + sq[2][tid] + sq[3][tid];
    float inv = 1.f / fmaxf(sqrtf(sumsq), EPSF);
    g_inv[n * P_ + pblk + tid] = inv;

    float l[KA];
    const float* orow = outp + tid * LDO1;
#pragma unroll
    for (int k = 0; k < KA; k++) l[k] = fmaf(orow[k], inv, bs[k]);
    float m = l[0];
#pragma unroll
    for (int k = 1; k < KA; k++) m = fmaxf(m, l[k]);
    float s = 0.f;
#pragma unroll
    for (int k = 0; k < KA; k++) { float e = __expf(l[k] - m); l[k] = e; s += e; }
    float rs = (1.f / s) * inv;     // fold inv into a

    __nv_bfloat16* ao = g_a + (size_t)n * KC * P_ + pblk + tid;
#pragma unroll
    for (int k = 0; k < KC; k++) ao[(size_t)k * P_] = __float2bfloat16(l[k] * rs);
}

// ============ GEMM2: aggregation — smem-free direct-fragment GEMM ============
// Per CTA: sample n, 64-channel tile.  D[k=64, c=64] = a'[k,p] * xb[c,p]^T,
// K = 1024 in 64 fragment steps.  All operands loaded as wmma fragments
// straight from global (a' row-major ldm=1024, xb col-major ldm=1024).
// No smem, no syncs: latency hidden by occupancy + 5 independent loads/iter.
__global__ void __launch_bounds__(128) k_gemm2() {
    int n = blockIdx.x;
    int cbase = blockIdx.y * 64;
    int tid = threadIdx.x;
    int wid = tid >> 5;
    if (blockIdx.y == 0 && tid == 0) g_nsq[n] = 0.f;   // reset before k_rownorm

    wmma::fragment<wmma::accumulator, 16, 16, 16, float> acc[4];
#pragma unroll
    for (int j = 0; j < 4; j++) wmma::fill_fragment(acc[j], 0.f);

    const __nv_bfloat16* ab = g_a + ((size_t)n * KC + 16 * wid) * P_;
    const __nv_bfloat16* xb = g_xb + ((size_t)n * C_ + cbase) * P_;

#pragma unroll 2
    for (int p0 = 0; p0 < P_; p0 += 16) {
        wmma::fragment<wmma::matrix_a, 16, 16, 16, __nv_bfloat16, wmma::row_major> af;
        wmma::fragment<wmma::matrix_b, 16, 16, 16, __nv_bfloat16, wmma::col_major> bf[4];
        wmma::load_matrix_sync(af, ab + p0, P_);
#pragma unroll
        for (int j = 0; j < 4; j++)
            wmma::load_matrix_sync(bf[j], xb + (size_t)(16 * j) * P_ + p0, P_);
#pragma unroll
        for (int j = 0; j < 4; j++)
            wmma::mma_sync(acc[j], af, bf[j], acc[j]);
    }

    float* dbase = g_agg + ((size_t)n * KC + 16 * wid) * C_ + cbase;
#pragma unroll
    for (int j = 0; j < 4; j++)
        wmma::store_matrix_sync(dbase + 16 * j, acc[j], C_, wmma::mem_row_major);
}

// ------- centroid subtract + per-row L2 (asum = sum a'/inv, inline) -------
__global__ void __launch_bounds__(128) k_rownorm(const float* __restrict__ cent,
                                                 float* __restrict__ out) {
    int n = blockIdx.x, k = blockIdx.y;
    int tid = threadIdx.x;
    __shared__ float red[4];
    __shared__ float bcast;

    // asum[n][k] = sum_p a[k][p] = sum_p a'[k][p] / inv[p]
    const __nv_bfloat16* ap = g_a + ((size_t)n * KC + k) * P_;
    const float* ivp = g_inv + n * P_ + 8 * tid;
    uint4 u = reinterpret_cast<const uint4*>(ap)[tid];
    float4 iv0 = *reinterpret_cast<const float4*>(ivp);
    float4 iv1 = *reinterpret_cast<const float4*>(ivp + 4);
    float asv;
    {
        uint32_t parts[4] = {u.x, u.y, u.z, u.w};
        float av[8];
#pragma unroll
        for (int i = 0; i < 4; i++) {
            __nv_bfloat162 h = *reinterpret_cast<__nv_bfloat162*>(&parts[i]);
            av[2 * i] = __low2float(h);
            av[2 * i + 1] = __high2float(h);
        }
        asv = av[0] / iv0.x + av[1] / iv0.y + av[2] / iv0.z + av[3] / iv0.w +
              av[4] / iv1.x + av[5] / iv1.y + av[6] / iv1.z + av[7] / iv1.w;
    }
#pragma unroll
    for (int o = 16; o; o >>= 1) asv += __shfl_xor_sync(0xFFFFFFFFu, asv, o);
    if ((tid & 31) == 0) red[tid >> 5] = asv;
    __syncthreads();
    if (tid == 0) bcast = red[0] + red[1] + red[2] + red[3];
    __syncthreads();
    float as = bcast;
    __syncthreads();   // protect red/bcast before reuse

    float v[4];
    float s = 0.f;
    size_t base = ((size_t)n * KC + k) * C_;
#pragma unroll
    for (int j = 0; j < 4; j++) {
        int c = tid + j * 128;
        float val = g_agg[base + c] - as * cent[k * C_ + c];
        v[j] = val;
        s = fmaf(val, val, s);
    }
#pragma unroll
    for (int o = 16; o; o >>= 1) s += __shfl_xor_sync(0xFFFFFFFFu, s, o);
    if ((tid & 31) == 0) red[tid >> 5] = s;
    __syncthreads();
    if (tid == 0) bcast = red[0] + red[1] + red[2] + red[3];
    __syncthreads();
    float total = bcast;
    float invn = 1.f / fmaxf(sqrtf(total), EPSF);
#pragma unroll
    for (int j = 0; j < 4; j++) {
        int c = tid + j * 128;
        out[(size_t)n * KC * C_ + (size_t)k * C_ + c] = v[j] * invn;
    }
    if (tid == 0) atomicAdd(&g_nsq[n], total * invn * invn);
}

// ---------------- global L2 normalize ----------------
__global__ void __launch_bounds__(256) k_final(float* __restrict__ out) {
    int n = blockIdx.x;
    float scale = 1.f / fmaxf(sqrtf(g_nsq[n]), EPSF);
    size_t idx = (size_t)n * (KC * C_) + ((size_t)blockIdx.y * 256 + threadIdx.x) * 4;
    float4* o = reinterpret_cast<float4*>(out + idx);
    float4 v = *o;
    v.x *= scale; v.y *= scale; v.z *= scale; v.w *= scale;
    *o = v;
}

// ---------------- launch ----------------
extern "C" void kernel_launch(void* const* d_in, const int* in_sizes, int n_in,
                              void* d_out, int out_size) {
    const float* x    = (const float*)d_in[0];
    const float* w    = (const float*)d_in[1];
    const float* b    = (const float*)d_in[2];
    const float* cent = (const float*)d_in[3];
    float* out = (float*)d_out;

    k_gemm1<<<dim3(N_, 8), 128>>>(x, w, b);
    k_gemm2<<<dim3(N_, 8), 128>>>();
    k_rownorm<<<dim3(N_, KC), 128>>>(cent, out);
    k_final<<<dim3(N_, 32), 256>>>(out);
}

// round 13
// speedup vs baseline: 1.6105x; 1.6105x over previous
#include <cuda_runtime.h>
#include <cuda_bf16.h>
#include <mma.h>
#include <math.h>
#include <stdint.h>

using namespace nvcuda;

#define N_   64
#define C_   512
#define P_   1024
#define KA   65
#define KC   64
#define EPSF 1e-12f

// ---------------- scratch (device globals: allocation-free) ----------------
__device__ float         g_inv[N_ * P_];             // per-pixel 1/||x||
__device__ __nv_bfloat16 g_a[N_ * KC * P_];          // a' = softmax * inv, bf16
__device__ __nv_bfloat16 g_xb[N_ * C_ * P_];         // bf16 copy of x (64 MB)
__device__ float         g_agg[N_ * KC * C_];
__device__ float         g_nsq[N_];

#define LDA1 72      // ws leading dim (k-major w tile), elems
#define LDXS 136     // [c][p] tile leading dim (128 px + 8 pad), elems
#define LDO1 84      // f32 out tile leading dim, elems

__device__ __forceinline__ uint32_t bfpack(float a, float b) {
    __nv_bfloat162 h = __floats2bfloat162_rn(a, b);
    return *reinterpret_cast<uint32_t*>(&h);
}

// ============ GEMM1: logits (tensor cores) + fused L2 norm + softmax ============
// Per CTA: sample n, 128-pixel tile.  D[p=128, k=80pad] = A[p,c] * W[k,c]^T,
// K = 512 channels in 8 chunks of 64.  x staged in native [c][p] layout;
// bf16(x) also streamed to g_xb for gemm2.  Epilogue stores a' = a * inv.
__global__ void __launch_bounds__(128) k_gemm1(const float* __restrict__ x,
                                               const float* __restrict__ w,
                                               const float* __restrict__ b) {
    // union: { ws[80][72]bf16 (11520B) | xa[64][136]bf16 (17408B) } vs outp[128][84]f32
    __shared__ __align__(16) char smbuf[43008];
    __shared__ float bs[KA];
    __shared__ float sq[4][128];                  // per-warp sumsq partials
    __nv_bfloat16* ws = reinterpret_cast<__nv_bfloat16*>(smbuf);
    __nv_bfloat16* xa = reinterpret_cast<__nv_bfloat16*>(smbuf + 11520);
    float* outp = reinterpret_cast<float*>(smbuf);

    int n = blockIdx.x;
    int pblk = blockIdx.y * 128;
    int tid = threadIdx.x;
    int wid = tid >> 5;
    int lane = tid & 31;
    int px4 = 4 * lane;                           // this thread's 4 pixels
    if (tid < KA) bs[tid] = b[tid];

    wmma::fragment<wmma::accumulator, 16, 16, 16, float> acc[2][5];
#pragma unroll
    for (int i = 0; i < 2; i++)
#pragma unroll
        for (int j = 0; j < 5; j++) wmma::fill_fragment(acc[i][j], 0.f);

    float sqa[4] = {0.f, 0.f, 0.f, 0.f};
    const float* xg = x + (size_t)n * C_ * P_ + pblk;
    __nv_bfloat16* xbg = g_xb + (size_t)n * C_ * P_ + pblk;
    uint32_t xr[32];   // packed bf16x2: 16 (row, 4px) pieces
    uint32_t wr[20];   // packed bf16x2: w chunk share

#define G1_LOAD(c0_)                                                           \
    do {                                                                       \
        _Pragma("unroll")                                                      \
        for (int i = 0; i < 16; i++) {                                         \
            int c = (c0_) + wid + 4 * i;                                       \
            float4 v = *reinterpret_cast<const float4*>(xg + (size_t)c * P_ + px4); \
            sqa[0] = fmaf(v.x, v.x, sqa[0]);                                   \
            sqa[1] = fmaf(v.y, v.y, sqa[1]);                                   \
            sqa[2] = fmaf(v.z, v.z, sqa[2]);                                   \
            sqa[3] = fmaf(v.w, v.w, sqa[3]);                                   \
            xr[2 * i]     = bfpack(v.x, v.y);                                  \
            xr[2 * i + 1] = bfpack(v.z, v.w);                                  \
        }                                                                      \
        _Pragma("unroll")                                                      \
        for (int i = 0; i < 20; i++) {                                         \
            int r = wid + 4 * i;                                               \
            float f0 = 0.f, f1 = 0.f;                                          \
            if (r < KA) {                                                      \
                float2 v = *reinterpret_cast<const float2*>(                   \
                    w + r * C_ + (c0_) + 2 * lane);                            \
                f0 = v.x; f1 = v.y;                                            \
            }                                                                  \
            wr[i] = bfpack(f0, f1);                                            \
        }                                                                      \
    } while (0)

    G1_LOAD(0);

    for (int ch = 0; ch < 8; ch++) {
        __syncthreads();   // previous mma done reading smem
#pragma unroll
        for (int i = 0; i < 16; i++) {
            int row = wid + 4 * i;    // local channel row
            uint2 pk = make_uint2(xr[2 * i], xr[2 * i + 1]);
            *reinterpret_cast<uint2*>(&xa[row * LDXS + px4]) = pk;
            // stream bf16(x) to global for gemm2 (coalesced 256B per warp row)
            *reinterpret_cast<uint2*>(xbg + (size_t)(ch * 64 + row) * P_ + px4) = pk;
        }
#pragma unroll
        for (int i = 0; i < 20; i++)
            *reinterpret_cast<uint32_t*>(&ws[(wid + 4 * i) * LDA1 + 2 * lane]) = wr[i];
        __syncthreads();

        if (ch < 7) G1_LOAD((ch + 1) * 64);   // LDGs in flight during mma below

#pragma unroll
        for (int ks = 0; ks < 4; ks++) {
            // A[p, c] tile is xa[c][p]: col_major, ldm = LDXS
            wmma::fragment<wmma::matrix_a, 16, 16, 16, __nv_bfloat16, wmma::col_major> af[2];
#pragma unroll
            for (int i = 0; i < 2; i++)
                wmma::load_matrix_sync(af[i], xa + (16 * ks) * LDXS + 32 * wid + 16 * i, LDXS);
#pragma unroll
            for (int j = 0; j < 5; j++) {
                wmma::fragment<wmma::matrix_b, 16, 16, 16, __nv_bfloat16, wmma::col_major> bf;
                wmma::load_matrix_sync(bf, ws + (16 * j) * LDA1 + 16 * ks, LDA1);
#pragma unroll
                for (int i = 0; i < 2; i++) wmma::mma_sync(acc[i][j], af[i], bf, acc[i][j]);
            }
        }
    }
#undef G1_LOAD

    // publish sumsq partials (4 pixels per thread, one slot per warp)
#pragma unroll
    for (int j = 0; j < 4; j++) sq[wid][px4 + j] = sqa[j];

    __syncthreads();   // smem reuse: bf16 tiles -> f32 out tile
#pragma unroll
    for (int i = 0; i < 2; i++)
#pragma unroll
        for (int j = 0; j < 5; j++)
            wmma::store_matrix_sync(outp + (32 * wid + 16 * i) * LDO1 + 16 * j,
                                    acc[i][j], LDO1, wmma::mem_row_major);
    __syncthreads();

    // epilogue: thread = pixel. logits = D*inv + b ; softmax ; store a' = a*inv
    float sumsq = sq[0][tid] + sq[1][tid] + sq[2][tid] + sq[3][tid];
    float inv = 1.f / fmaxf(sqrtf(sumsq), EPSF);
    g_inv[n * P_ + pblk + tid] = inv;

    float l[KA];
    const float* orow = outp + tid * LDO1;
#pragma unroll
    for (int k = 0; k < KA; k++) l[k] = fmaf(orow[k], inv, bs[k]);
    float m = l[0];
#pragma unroll
    for (int k = 1; k < KA; k++) m = fmaxf(m, l[k]);
    float s = 0.f;
#pragma unroll
    for (int k = 0; k < KA; k++) { float e = __expf(l[k] - m); l[k] = e; s += e; }
    float rs = (1.f / s) * inv;     // fold inv into a

    __nv_bfloat16* ao = g_a + (size_t)n * KC * P_ + pblk + tid;
#pragma unroll
    for (int k = 0; k < KC; k++) ao[(size_t)k * P_] = __float2bfloat16(l[k] * rs);
}

// ============ GEMM2: aggregation, R11 smem pipeline, staged from bf16 cache ============
// Per CTA: sample n, 64-channel tile.  D[k=64, c=64] = a'[k,p] * xb[c,p]^T,
// K = 1024 pixels in 8 chunks of 128.  Staging = pure uint2 copy from g_xb
// (no cvt, no scaling).  Conflict-free STS.64; fragments from smem.
__global__ void __launch_bounds__(128) k_gemm2() {
    __shared__ __align__(16) __nv_bfloat16 xs[64 * LDXS];   // [c][p-chunk], 17408B

    int n = blockIdx.x;
    int cbase = blockIdx.y * 64;
    int tid = threadIdx.x;
    int wid = tid >> 5;
    int lane = tid & 31;
    int px4 = 4 * lane;
    if (blockIdx.y == 0 && tid == 0) g_nsq[n] = 0.f;   // reset before k_rownorm

    wmma::fragment<wmma::accumulator, 16, 16, 16, float> acc[4];
#pragma unroll
    for (int j = 0; j < 4; j++) wmma::fill_fragment(acc[j], 0.f);

    const __nv_bfloat16* abase = g_a + ((size_t)n * KC + 16 * wid) * P_;
    const __nv_bfloat16* xbg = g_xb + ((size_t)n * C_ + cbase) * P_;
    uint2 xr[16];

#define G2_LOAD(p0_)                                                           \
    do {                                                                       \
        _Pragma("unroll")                                                      \
        for (int i = 0; i < 16; i++) {                                         \
            int r = wid + 4 * i;                                               \
            xr[i] = *reinterpret_cast<const uint2*>(                           \
                xbg + (size_t)r * P_ + (p0_) + px4);                           \
        }                                                                      \
    } while (0)

    G2_LOAD(0);

    for (int ch = 0; ch < 8; ch++) {
        __syncthreads();
#pragma unroll
        for (int i = 0; i < 16; i++) {
            int row = wid + 4 * i;
            *reinterpret_cast<uint2*>(&xs[row * LDXS + px4]) = xr[i];
        }
        __syncthreads();

        int p0 = ch * 128;
        if (ch < 7) G2_LOAD(p0 + 128);   // LDGs in flight during mma below

        wmma::fragment<wmma::matrix_a, 16, 16, 16, __nv_bfloat16, wmma::row_major> af[8];
#pragma unroll
        for (int ks = 0; ks < 8; ks++)
            wmma::load_matrix_sync(af[ks], abase + p0 + 16 * ks, P_);
#pragma unroll
        for (int ks = 0; ks < 8; ks++) {
#pragma unroll
            for (int j = 0; j < 4; j++) {
                // B[p, c] tile is xs[c][p]: col_major, ldm = LDXS
                wmma::fragment<wmma::matrix_b, 16, 16, 16, __nv_bfloat16, wmma::col_major> bf;
                wmma::load_matrix_sync(bf, xs + (16 * j) * LDXS + 16 * ks, LDXS);
                wmma::mma_sync(acc[j], af[ks], bf, acc[j]);
            }
        }
    }
#undef G2_LOAD

    float* dbase = g_agg + ((size_t)n * KC + 16 * wid) * C_ + cbase;
#pragma unroll
    for (int j = 0; j < 4; j++)
        wmma::store_matrix_sync(dbase + 16 * j, acc[j], C_, wmma::mem_row_major);
}

// ------- centroid subtract + per-row L2 (asum = sum a'/inv, inline) -------
__global__ void __launch_bounds__(128) k_rownorm(const float* __restrict__ cent,
                                                 float* __restrict__ out) {
    int n = blockIdx.x, k = blockIdx.y;
    int tid = threadIdx.x;
    __shared__ float red[4];
    __shared__ float bcast;

    // asum[n][k] = sum_p a[k][p] = sum_p a'[k][p] / inv[p]
    const __nv_bfloat16* ap = g_a + ((size_t)n * KC + k) * P_;
    const float* ivp = g_inv + n * P_ + 8 * tid;
    uint4 u = reinterpret_cast<const uint4*>(ap)[tid];
    float4 iv0 = *reinterpret_cast<const float4*>(ivp);
    float4 iv1 = *reinterpret_cast<const float4*>(ivp + 4);
    float asv;
    {
        uint32_t parts[4] = {u.x, u.y, u.z, u.w};
        float av[8];
#pragma unroll
        for (int i = 0; i < 4; i++) {
            __nv_bfloat162 h = *reinterpret_cast<__nv_bfloat162*>(&parts[i]);
            av[2 * i] = __low2float(h);
            av[2 * i + 1] = __high2float(h);
        }
        asv = av[0] / iv0.x + av[1] / iv0.y + av[2] / iv0.z + av[3] / iv0.w +
              av[4] / iv1.x + av[5] / iv1.y + av[6] / iv1.z + av[7] / iv1.w;
    }
#pragma unroll
    for (int o = 16; o; o >>= 1) asv += __shfl_xor_sync(0xFFFFFFFFu, asv, o);
    if ((tid & 31) == 0) red[tid >> 5] = asv;
    __syncthreads();
    if (tid == 0) bcast = red[0] + red[1] + red[2] + red[3];
    __syncthreads();
    float as = bcast;
    __syncthreads();   // protect red/bcast before reuse

    float v[4];
    float s = 0.f;
    size_t base = ((size_t)n * KC + k) * C_;
#pragma unroll
    for (int j = 0; j < 4; j++) {
        int c = tid + j * 128;
        float val = g_agg[base + c] - as * cent[k * C_ + c];
        v[j] = val;
        s = fmaf(val, val, s);
    }
#pragma unroll
    for (int o = 16; o; o >>= 1) s += __shfl_xor_sync(0xFFFFFFFFu, s, o);
    if ((tid & 31) == 0) red[tid >> 5] = s;
    __syncthreads();
    if (tid == 0) bcast = red[0] + red[1] + red[2] + red[3];
    __syncthreads();
    float total = bcast;
    float invn = 1.f / fmaxf(sqrtf(total), EPSF);
#pragma unroll
    for (int j = 0; j < 4; j++) {
        int c = tid + j * 128;
        out[(size_t)n * KC * C_ + (size_t)k * C_ + c] = v[j] * invn;
    }
    if (tid == 0) atomicAdd(&g_nsq[n], total * invn * invn);
}

// ---------------- global L2 normalize ----------------
__global__ void __launch_bounds__(256) k_final(float* __restrict__ out) {
    int n = blockIdx.x;
    float scale = 1.f / fmaxf(sqrtf(g_nsq[n]), EPSF);
    size_t idx = (size_t)n * (KC * C_) + ((size_t)blockIdx.y * 256 + threadIdx.x) * 4;
    float4* o = reinterpret_cast<float4*>(out + idx);
    float4 v = *o;
    v.x *= scale; v.y *= scale; v.z *= scale; v.w *= scale;
    *o = v;
}

// ---------------- launch ----------------
extern "C" void kernel_launch(void* const* d_in, const int* in_sizes, int n_in,
                              void* d_out, int out_size) {
    const float* x    = (const float*)d_in[0];
    const float* w    = (const float*)d_in[1];
    const float* b    = (const float*)d_in[2];
    const float* cent = (const float*)d_in[3];
    float* out = (float*)d_out;

    k_gemm1<<<dim3(N_, 8), 128>>>(x, w, b);
    k_gemm2<<<dim3(N_, 8), 128>>>();
    k_rownorm<<<dim3(N_, KC), 128>>>(cent, out);
    k_final<<<dim3(N_, 32), 256>>>(out);
}

// round 14
// speedup vs baseline: 1.6177x; 1.0044x over previous
#include <cuda_runtime.h>
#include <cuda_bf16.h>
#include <mma.h>
#include <math.h>
#include <stdint.h>

using namespace nvcuda;

#define N_   64
#define C_   512
#define P_   1024
#define KA   65
#define KC   64
#define EPSF 1e-12f

// ---------------- scratch (device globals: allocation-free) ----------------
__device__ float         g_inv[N_ * P_];             // per-pixel 1/||x||
__device__ __nv_bfloat16 g_a[N_ * KC * P_];          // a' = softmax * inv, bf16
__device__ __nv_bfloat16 g_xb[N_ * C_ * P_];         // bf16 copy of x (64 MB)
__device__ float         g_agg[N_ * KC * C_];
__device__ float         g_nsq[N_];

#define LDA1 72      // ws leading dim (k-major w tile), elems
#define LDXS 136     // [c][p] tile leading dim (128 px + 8 pad), elems
#define LDO1 84      // f32 out tile leading dim, elems

__device__ __forceinline__ uint32_t bfpack(float a, float b) {
    __nv_bfloat162 h = __floats2bfloat162_rn(a, b);
    return *reinterpret_cast<uint32_t*>(&h);
}

// ============ GEMM1: logits (tensor cores) + fused L2 norm + softmax ============
// Per CTA: sample n, 128-pixel tile, 256 threads (8 warps).
// D[p=128, k=80pad] = A[p,c] * W[k,c]^T, K = 512 in 8 chunks of 64.
// Warp w owns pixel rows [16w, 16w+16) -> 1x5 fragment row, halving the
// per-warp serial mma chain vs the 4-warp version.  bf16(x) streamed to g_xb.
__global__ void __launch_bounds__(256) k_gemm1(const float* __restrict__ x,
                                               const float* __restrict__ w,
                                               const float* __restrict__ b) {
    // union: { ws[80][72]bf16 (11520B) | xa[64][136]bf16 (17408B) } vs outp[128][84]f32
    __shared__ __align__(16) char smbuf[43008];
    __shared__ float bs[KA];
    __shared__ float sq[8][128];                  // per-warp sumsq partials
    __nv_bfloat16* ws = reinterpret_cast<__nv_bfloat16*>(smbuf);
    __nv_bfloat16* xa = reinterpret_cast<__nv_bfloat16*>(smbuf + 11520);
    float* outp = reinterpret_cast<float*>(smbuf);

    int n = blockIdx.x;
    int pblk = blockIdx.y * 128;
    int tid = threadIdx.x;
    int wid = tid >> 5;          // 0..7
    int lane = tid & 31;
    int px4 = 4 * lane;          // 4 pixels within the 128-px tile
    if (tid < KA) bs[tid] = b[tid];

    wmma::fragment<wmma::accumulator, 16, 16, 16, float> acc[5];
#pragma unroll
    for (int j = 0; j < 5; j++) wmma::fill_fragment(acc[j], 0.f);

    float sqa[4] = {0.f, 0.f, 0.f, 0.f};
    const float* xg = x + (size_t)n * C_ * P_ + pblk;
    __nv_bfloat16* xbg = g_xb + (size_t)n * C_ * P_ + pblk;
    uint32_t xr[16];   // packed bf16x2: 8 (row, 4px) pieces
    uint32_t wr[10];   // packed bf16x2: w chunk share

#define G1_LOAD(c0_)                                                           \
    do {                                                                       \
        _Pragma("unroll")                                                      \
        for (int i = 0; i < 8; i++) {                                          \
            int c = (c0_) + wid + 8 * i;                                       \
            float4 v = *reinterpret_cast<const float4*>(xg + (size_t)c * P_ + px4); \
            sqa[0] = fmaf(v.x, v.x, sqa[0]);                                   \
            sqa[1] = fmaf(v.y, v.y, sqa[1]);                                   \
            sqa[2] = fmaf(v.z, v.z, sqa[2]);                                   \
            sqa[3] = fmaf(v.w, v.w, sqa[3]);                                   \
            xr[2 * i]     = bfpack(v.x, v.y);                                  \
            xr[2 * i + 1] = bfpack(v.z, v.w);                                  \
        }                                                                      \
        _Pragma("unroll")                                                      \
        for (int i = 0; i < 10; i++) {                                         \
            int r = wid + 8 * i;                                               \
            float f0 = 0.f, f1 = 0.f;                                          \
            if (r < KA) {                                                      \
                float2 v = *reinterpret_cast<const float2*>(                   \
                    w + r * C_ + (c0_) + 2 * lane);                            \
                f0 = v.x; f1 = v.y;                                            \
            }                                                                  \
            wr[i] = bfpack(f0, f1);                                            \
        }                                                                      \
    } while (0)

    G1_LOAD(0);

    for (int ch = 0; ch < 8; ch++) {
        __syncthreads();   // previous mma done reading smem
#pragma unroll
        for (int i = 0; i < 8; i++) {
            int row = wid + 8 * i;    // local channel row
            uint2 pk = make_uint2(xr[2 * i], xr[2 * i + 1]);
            *reinterpret_cast<uint2*>(&xa[row * LDXS + px4]) = pk;
            // stream bf16(x) to global for gemm2 (coalesced 256B per warp row)
            *reinterpret_cast<uint2*>(xbg + (size_t)(ch * 64 + row) * P_ + px4) = pk;
        }
#pragma unroll
        for (int i = 0; i < 10; i++)
            *reinterpret_cast<uint32_t*>(&ws[(wid + 8 * i) * LDA1 + 2 * lane]) = wr[i];
        __syncthreads();

        if (ch < 7) G1_LOAD((ch + 1) * 64);   // LDGs in flight during mma below

#pragma unroll
        for (int ks = 0; ks < 4; ks++) {
            // A[p, c] tile is xa[c][p]: col_major, ldm = LDXS; warp w -> p rows 16w
            wmma::fragment<wmma::matrix_a, 16, 16, 16, __nv_bfloat16, wmma::col_major> af;
            wmma::load_matrix_sync(af, xa + (16 * ks) * LDXS + 16 * wid, LDXS);
#pragma unroll
            for (int j = 0; j < 5; j++) {
                wmma::fragment<wmma::matrix_b, 16, 16, 16, __nv_bfloat16, wmma::col_major> bf;
                wmma::load_matrix_sync(bf, ws + (16 * j) * LDA1 + 16 * ks, LDA1);
                wmma::mma_sync(acc[j], af, bf, acc[j]);
            }
        }
    }
#undef G1_LOAD

    // publish sumsq partials (4 pixels per thread, one slot per warp)
#pragma unroll
    for (int j = 0; j < 4; j++) sq[wid][px4 + j] = sqa[j];

    __syncthreads();   // smem reuse: bf16 tiles -> f32 out tile
#pragma unroll
    for (int j = 0; j < 5; j++)
        wmma::store_matrix_sync(outp + (16 * wid) * LDO1 + 16 * j,
                                acc[j], LDO1, wmma::mem_row_major);
    __syncthreads();

    // epilogue on threads 0-127: thread = pixel.  logits = D*inv + b ; softmax ;
    // store a' = a * inv (inv folded so gemm2 uses raw bf16 x).
    if (tid < 128) {
        float sumsq = 0.f;
#pragma unroll
        for (int wv = 0; wv < 8; wv++) sumsq += sq[wv][tid];
        float inv = 1.f / fmaxf(sqrtf(sumsq), EPSF);
        g_inv[n * P_ + pblk + tid] = inv;

        float l[KA];
        const float* orow = outp + tid * LDO1;
#pragma unroll
        for (int k = 0; k < KA; k++) l[k] = fmaf(orow[k], inv, bs[k]);
        float m = l[0];
#pragma unroll
        for (int k = 1; k < KA; k++) m = fmaxf(m, l[k]);
        float s = 0.f;
#pragma unroll
        for (int k = 0; k < KA; k++) { float e = __expf(l[k] - m); l[k] = e; s += e; }
        float rs = (1.f / s) * inv;     // fold inv into a

        __nv_bfloat16* ao = g_a + (size_t)n * KC * P_ + pblk + tid;
#pragma unroll
        for (int k = 0; k < KC; k++) ao[(size_t)k * P_] = __float2bfloat16(l[k] * rs);
    }
}

// ============ GEMM2: aggregation, smem pipeline, staged from bf16 cache ============
// Per CTA: sample n, 64-channel tile.  D[k=64, c=64] = a'[k,p] * xb[c,p]^T,
// K = 1024 pixels in 8 chunks of 128.  Staging = pure uint2 copy from g_xb.
__global__ void __launch_bounds__(128) k_gemm2() {
    __shared__ __align__(16) __nv_bfloat16 xs[64 * LDXS];   // [c][p-chunk], 17408B

    int n = blockIdx.x;
    int cbase = blockIdx.y * 64;
    int tid = threadIdx.x;
    int wid = tid >> 5;
    int lane = tid & 31;
    int px4 = 4 * lane;
    if (blockIdx.y == 0 && tid == 0) g_nsq[n] = 0.f;   // reset before k_rownorm

    wmma::fragment<wmma::accumulator, 16, 16, 16, float> acc[4];
#pragma unroll
    for (int j = 0; j < 4; j++) wmma::fill_fragment(acc[j], 0.f);

    const __nv_bfloat16* abase = g_a + ((size_t)n * KC + 16 * wid) * P_;
    const __nv_bfloat16* xbg = g_xb + ((size_t)n * C_ + cbase) * P_;
    uint2 xr[16];

#define G2_LOAD(p0_)                                                           \
    do {                                                                       \
        _Pragma("unroll")                                                      \
        for (int i = 0; i < 16; i++) {                                         \
            int r = wid + 4 * i;                                               \
            xr[i] = *reinterpret_cast<const uint2*>(                           \
                xbg + (size_t)r * P_ + (p0_) + px4);                           \
        }                                                                      \
    } while (0)

    G2_LOAD(0);

    for (int ch = 0; ch < 8; ch++) {
        __syncthreads();
#pragma unroll
        for (int i = 0; i < 16; i++) {
            int row = wid + 4 * i;
            *reinterpret_cast<uint2*>(&xs[row * LDXS + px4]) = xr[i];
        }
        __syncthreads();

        int p0 = ch * 128;
        if (ch < 7) G2_LOAD(p0 + 128);   // LDGs in flight during mma below

        wmma::fragment<wmma::matrix_a, 16, 16, 16, __nv_bfloat16, wmma::row_major> af[8];
#pragma unroll
        for (int ks = 0; ks < 8; ks++)
            wmma::load_matrix_sync(af[ks], abase + p0 + 16 * ks, P_);
#pragma unroll
        for (int ks = 0; ks < 8; ks++) {
#pragma unroll
            for (int j = 0; j < 4; j++) {
                // B[p, c] tile is xs[c][p]: col_major, ldm = LDXS
                wmma::fragment<wmma::matrix_b, 16, 16, 16, __nv_bfloat16, wmma::col_major> bf;
                wmma::load_matrix_sync(bf, xs + (16 * j) * LDXS + 16 * ks, LDXS);
                wmma::mma_sync(acc[j], af[ks], bf, acc[j]);
            }
        }
    }
#undef G2_LOAD

    float* dbase = g_agg + ((size_t)n * KC + 16 * wid) * C_ + cbase;
#pragma unroll
    for (int j = 0; j < 4; j++)
        wmma::store_matrix_sync(dbase + 16 * j, acc[j], C_, wmma::mem_row_major);
}

// ------- centroid subtract + per-row L2 (asum = sum a'/inv, inline) -------
__global__ void __launch_bounds__(128) k_rownorm(const float* __restrict__ cent,
                                                 float* __restrict__ out) {
    int n = blockIdx.x, k = blockIdx.y;
    int tid = threadIdx.x;
    __shared__ float red[4];
    __shared__ float bcast;

    // asum[n][k] = sum_p a[k][p] = sum_p a'[k][p] / inv[p]
    const __nv_bfloat16* ap = g_a + ((size_t)n * KC + k) * P_;
    const float* ivp = g_inv + n * P_ + 8 * tid;
    uint4 u = reinterpret_cast<const uint4*>(ap)[tid];
    float4 iv0 = *reinterpret_cast<const float4*>(ivp);
    float4 iv1 = *reinterpret_cast<const float4*>(ivp + 4);
    float asv;
    {
        uint32_t parts[4] = {u.x, u.y, u.z, u.w};
        float av[8];
#pragma unroll
        for (int i = 0; i < 4; i++) {
            __nv_bfloat162 h = *reinterpret_cast<__nv_bfloat162*>(&parts[i]);
            av[2 * i] = __low2float(h);
            av[2 * i + 1] = __high2float(h);
        }
        asv = av[0] / iv0.x + av[1] / iv0.y + av[2] / iv0.z + av[3] / iv0.w +
              av[4] / iv1.x + av[5] / iv1.y + av[6] / iv1.z + av[7] / iv1.w;
    }
#pragma unroll
    for (int o = 16; o; o >>= 1) asv += __shfl_xor_sync(0xFFFFFFFFu, asv, o);
    if ((tid & 31) == 0) red[tid >> 5] = asv;
    __syncthreads();
    if (tid == 0) bcast = red[0] + red[1] + red[2] + red[3];
    __syncthreads();
    float as = bcast;
    __syncthreads();   // protect red/bcast before reuse

    float v[4];
    float s = 0.f;
    size_t base = ((size_t)n * KC + k) * C_;
#pragma unroll
    for (int j = 0; j < 4; j++) {
        int c = tid + j * 128;
        float val = g_agg[base + c] - as * cent[k * C_ + c];
        v[j] = val;
        s = fmaf(val, val, s);
    }
#pragma unroll
    for (int o = 16; o; o >>= 1) s += __shfl_xor_sync(0xFFFFFFFFu, s, o);
    if ((tid & 31) == 0) red[tid >> 5] = s;
    __syncthreads();
    if (tid == 0) bcast = red[0] + red[1] + red[2] + red[3];
    __syncthreads();
    float total = bcast;
    float invn = 1.f / fmaxf(sqrtf(total), EPSF);
#pragma unroll
    for (int j = 0; j < 4; j++) {
        int c = tid + j * 128;
        out[(size_t)n * KC * C_ + (size_t)k * C_ + c] = v[j] * invn;
    }
    if (tid == 0) atomicAdd(&g_nsq[n], total * invn * invn);
}

// ---------------- global L2 normalize ----------------
__global__ void __launch_bounds__(256) k_final(float* __restrict__ out) {
    int n = blockIdx.x;
    float scale = 1.f / fmaxf(sqrtf(g_nsq[n]), EPSF);
    size_t idx = (size_t)n * (KC * C_) + ((size_t)blockIdx.y * 256 + threadIdx.x) * 4;
    float4* o = reinterpret_cast<float4*>(out + idx);
    float4 v = *o;
    v.x *= scale; v.y *= scale; v.z *= scale; v.w *= scale;
    *o = v;
}

// ---------------- launch ----------------
extern "C" void kernel_launch(void* const* d_in, const int* in_sizes, int n_in,
                              void* d_out, int out_size) {
    const float* x    = (const float*)d_in[0];
    const float* w    = (const float*)d_in[1];
    const float* b    = (const float*)d_in[2];
    const float* cent = (const float*)d_in[3];
    float* out = (float*)d_out;

    k_gemm1<<<dim3(N_, 8), 256>>>(x, w, b);
    k_gemm2<<<dim3(N_, 8), 128>>>();
    k_rownorm<<<dim3(N_, KC), 128>>>(cent, out);
    k_final<<<dim3(N_, 32), 256>>>(out);
}